// round 1
// baseline (speedup 1.0000x reference)
#include <cuda_runtime.h>
#include <cstdint>

// ---------------------------------------------------------------------------
// DiagonalSSMBlock: rmsnorm -> Bu GEMM -> diagonal scan -> C GEMM (+res+Dskip*u)
//                   -> rmsnorm -> dual SwiGLU GEMM -> down GEMM (+res)
// All fp32. GEMM inner loops use packed fma.rn.f32x2 (Blackwell) to reach the
// full 128-FMA-lane/cyc/SM fp32 rate (plain 3-reg FFMA is half rate on sm_103a).
// ---------------------------------------------------------------------------

#define DEV_INLINE __device__ __forceinline__

constexpr int B_SZ  = 4;
constexpr int T_LEN = 4096;
constexpr int DM    = 1024;
constexpr int NS    = 256;
constexpr int DFF   = 2736;
constexpr int MROWS = B_SZ * T_LEN;   // 16384
constexpr float EPSN = 1e-6f;

constexpr int CLEN   = 128;           // scan chunk length (power of two)
constexpr int NCHUNK = T_LEN / CLEN;  // 32

// ------------------------------- scratch ----------------------------------
__device__ float g_u [(size_t)MROWS * DM];
__device__ float g_Bu[(size_t)MROWS * NS];
__device__ float g_hs[(size_t)MROWS * NS];
__device__ float g_x1[(size_t)MROWS * DM];
__device__ float g_z [(size_t)MROWS * DM];
__device__ float g_g [(size_t)MROWS * DFF];
__device__ float g_Hc[B_SZ * NCHUNK * NS];
__device__ float g_Hs[B_SZ * NCHUNK * NS];

// --------------------------- f32x2 helpers --------------------------------
using ull = unsigned long long;

DEV_INLINE ull pack2(float lo, float hi) {
    ull r;
    asm("mov.b64 %0, {%1, %2};" : "=l"(r) : "f"(lo), "f"(hi));
    return r;
}
DEV_INLINE ull fma2(ull a, ull b, ull c) {
    ull d;
    asm("fma.rn.f32x2 %0, %1, %2, %3;" : "=l"(d) : "l"(a), "l"(b), "l"(c));
    return d;
}
DEV_INLINE float2 unpk(ull v) {
    float lo, hi;
    asm("mov.b64 {%0, %1}, %2;" : "=f"(lo), "=f"(hi) : "l"(v));
    return make_float2(lo, hi);
}

// ------------------------------- rmsnorm -----------------------------------
__global__ void __launch_bounds__(256)
rmsnorm_kernel(const float* __restrict__ x, const float* __restrict__ w,
               float* __restrict__ out)
{
    const int row = blockIdx.x;
    const int tid = threadIdx.x;
    const float4* xr = reinterpret_cast<const float4*>(x + (size_t)row * DM);
    float4 v = xr[tid];
    float ss = v.x*v.x + v.y*v.y + v.z*v.z + v.w*v.w;
    #pragma unroll
    for (int o = 16; o; o >>= 1) ss += __shfl_xor_sync(0xffffffffu, ss, o);
    __shared__ float red[8];
    if ((tid & 31) == 0) red[tid >> 5] = ss;
    __syncthreads();
    float tot = red[0]+red[1]+red[2]+red[3]+red[4]+red[5]+red[6]+red[7];
    float inv = rsqrtf(tot * (1.0f / (float)DM) + EPSN);
    float4 wv = reinterpret_cast<const float4*>(w)[tid];
    float4 o4 = make_float4(v.x*inv*wv.x, v.y*inv*wv.y, v.z*inv*wv.z, v.w*inv*wv.w);
    reinterpret_cast<float4*>(out + (size_t)row * DM)[tid] = o4;
}

// --------------------------- chunked diagonal scan --------------------------
DEV_INLINE float lam_of(const float* ll, int n) {
    return 1.0f / (1.0f + expf(-ll[n]));
}

// local in-chunk scan; writes local hs and per-chunk carry
__global__ void __launch_bounds__(NS)
scan_local_kernel(const float* __restrict__ Bu, float* __restrict__ hs,
                  float* __restrict__ Hc, const float* __restrict__ ll)
{
    const int bc = blockIdx.x;             // b * NCHUNK + c
    const int b  = bc / NCHUNK;
    const int c  = bc % NCHUNK;
    const int n  = threadIdx.x;
    const float lam = lam_of(ll, n);
    size_t base = ((size_t)b * T_LEN + (size_t)c * CLEN) * NS + n;
    float h = 0.0f;
    #pragma unroll 4
    for (int i = 0; i < CLEN; ++i) {
        h = fmaf(lam, h, Bu[base + (size_t)i * NS]);
        hs[base + (size_t)i * NS] = h;
    }
    Hc[bc * NS + n] = h;
}

// scan of chunk carries (entering-state per chunk)
__global__ void __launch_bounds__(NS)
scan_carry_kernel(const float* __restrict__ Hc, float* __restrict__ Hs,
                  const float* __restrict__ ll)
{
    const int b = blockIdx.x;
    const int n = threadIdx.x;
    const float lam = lam_of(ll, n);
    float lamP = lam;
    #pragma unroll
    for (int j = 0; j < 7; ++j) lamP *= lamP;   // lam^128 == lam^CLEN
    float h = 0.0f;
    for (int c = 0; c < NCHUNK; ++c) {
        Hs[(b * NCHUNK + c) * NS + n] = h;      // state entering chunk c
        h = fmaf(lamP, h, Hc[(b * NCHUNK + c) * NS + n]);
    }
}

// fixup: hs += lam^(i+1) * entering_state
__global__ void __launch_bounds__(NS)
scan_fix_kernel(float* __restrict__ hs, const float* __restrict__ Hs,
                const float* __restrict__ ll)
{
    const int bc = blockIdx.x;
    const int b  = bc / NCHUNK;
    const int c  = bc % NCHUNK;
    if (c == 0) return;                          // entering state is zero
    const int n  = threadIdx.x;
    const float lam = lam_of(ll, n);
    const float h0 = Hs[bc * NS + n];
    size_t base = ((size_t)b * T_LEN + (size_t)c * CLEN) * NS + n;
    float p = lam;
    #pragma unroll 4
    for (int i = 0; i < CLEN; ++i) {
        size_t idx = base + (size_t)i * NS;
        hs[idx] = fmaf(p, h0, hs[idx]);
        p *= lam;
    }
}

// ------------------------------ single GEMM --------------------------------
// C[M,N] = A[M,K] @ B[N,K]^T, row-major everywhere. BM=128 BN=128 BK=16,
// 256 threads, 8x8 per thread via f32x2. M%128==0, N%128==0, K%16==0 required.
constexpr int BM = 128, BN = 128, BK = 16;

enum { EPI_NONE = 0, EPI_SSM = 1, EPI_ADD = 2 };

template <int EPI>
__global__ void __launch_bounds__(256)
gemm_f32x2(const float* __restrict__ A, const float* __restrict__ Bm,
           float* __restrict__ C, int M, int N, int K,
           const float* __restrict__ res, const float* __restrict__ uaux,
           const float* __restrict__ dskip)
{
    __shared__ float As[BK][BM + 4];
    __shared__ float Bs[BK][BN + 4];

    const int tid = threadIdx.x;
    const int mBase = blockIdx.y * BM;
    const int nBase = blockIdx.x * BN;
    const int tx = tid & 15;        // n: 8 cols at tx*8
    const int ty = tid >> 4;        // m: 8 rows at ty*8
    const int lr = tid >> 2;        // load row 0..63 (and +64)
    const int lq = tid & 3;         // k-quad

    const float* pa0 = A  + (size_t)(mBase + lr)      * K + lq * 4;
    const float* pa1 = A  + (size_t)(mBase + lr + 64) * K + lq * 4;
    const float* pb0 = Bm + (size_t)(nBase + lr)      * K + lq * 4;
    const float* pb1 = Bm + (size_t)(nBase + lr + 64) * K + lq * 4;

    float4 ra0 = *reinterpret_cast<const float4*>(pa0);
    float4 ra1 = *reinterpret_cast<const float4*>(pa1);
    float4 rb0 = *reinterpret_cast<const float4*>(pb0);
    float4 rb1 = *reinterpret_cast<const float4*>(pb1);

    ull acc[8][4];
    #pragma unroll
    for (int i = 0; i < 8; ++i)
        #pragma unroll
        for (int j = 0; j < 4; ++j) acc[i][j] = 0ull;

    const int KT = K / BK;
    for (int kt = 0; kt < KT; ++kt) {
        // commit staged tile to smem (transposed: [k][row])
        As[lq*4+0][lr]      = ra0.x; As[lq*4+1][lr]      = ra0.y;
        As[lq*4+2][lr]      = ra0.z; As[lq*4+3][lr]      = ra0.w;
        As[lq*4+0][lr + 64] = ra1.x; As[lq*4+1][lr + 64] = ra1.y;
        As[lq*4+2][lr + 64] = ra1.z; As[lq*4+3][lr + 64] = ra1.w;
        Bs[lq*4+0][lr]      = rb0.x; Bs[lq*4+1][lr]      = rb0.y;
        Bs[lq*4+2][lr]      = rb0.z; Bs[lq*4+3][lr]      = rb0.w;
        Bs[lq*4+0][lr + 64] = rb1.x; Bs[lq*4+1][lr + 64] = rb1.y;
        Bs[lq*4+2][lr + 64] = rb1.z; Bs[lq*4+3][lr + 64] = rb1.w;
        __syncthreads();

        if (kt + 1 < KT) {  // prefetch next tile while computing
            ra0 = *reinterpret_cast<const float4*>(pa0 + (size_t)(kt + 1) * BK);
            ra1 = *reinterpret_cast<const float4*>(pa1 + (size_t)(kt + 1) * BK);
            rb0 = *reinterpret_cast<const float4*>(pb0 + (size_t)(kt + 1) * BK);
            rb1 = *reinterpret_cast<const float4*>(pb1 + (size_t)(kt + 1) * BK);
        }

        #pragma unroll
        for (int k = 0; k < BK; ++k) {
            float4 a0 = *reinterpret_cast<const float4*>(&As[k][ty * 8]);
            float4 a1 = *reinterpret_cast<const float4*>(&As[k][ty * 8 + 4]);
            ulonglong2 q0 = *reinterpret_cast<const ulonglong2*>(&Bs[k][tx * 8]);
            ulonglong2 q1 = *reinterpret_cast<const ulonglong2*>(&Bs[k][tx * 8 + 4]);
            ull bb[4] = {q0.x, q0.y, q1.x, q1.y};
            ull aa[8] = {pack2(a0.x, a0.x), pack2(a0.y, a0.y),
                         pack2(a0.z, a0.z), pack2(a0.w, a0.w),
                         pack2(a1.x, a1.x), pack2(a1.y, a1.y),
                         pack2(a1.z, a1.z), pack2(a1.w, a1.w)};
            #pragma unroll
            for (int i = 0; i < 8; ++i)
                #pragma unroll
                for (int j = 0; j < 4; ++j)
                    acc[i][j] = fma2(aa[i], bb[j], acc[i][j]);
        }
        __syncthreads();
    }

    // ---------------- epilogue ----------------
    const int colb = nBase + tx * 8;
    float4 d0, d1;
    if (EPI == EPI_SSM) {
        d0 = *reinterpret_cast<const float4*>(dskip + colb);
        d1 = *reinterpret_cast<const float4*>(dskip + colb + 4);
    }
    #pragma unroll
    for (int i = 0; i < 8; ++i) {
        const int row = mBase + ty * 8 + i;
        const size_t off = (size_t)row * N + colb;
        float2 f0 = unpk(acc[i][0]), f1 = unpk(acc[i][1]);
        float2 f2 = unpk(acc[i][2]), f3 = unpk(acc[i][3]);
        float4 c0 = make_float4(f0.x, f0.y, f1.x, f1.y);
        float4 c1 = make_float4(f2.x, f2.y, f3.x, f3.y);
        if (EPI == EPI_SSM) {
            float4 r0 = *reinterpret_cast<const float4*>(res + off);
            float4 r1 = *reinterpret_cast<const float4*>(res + off + 4);
            float4 u0 = *reinterpret_cast<const float4*>(uaux + off);
            float4 u1 = *reinterpret_cast<const float4*>(uaux + off + 4);
            c0.x = r0.x + c0.x + d0.x * u0.x; c0.y = r0.y + c0.y + d0.y * u0.y;
            c0.z = r0.z + c0.z + d0.z * u0.z; c0.w = r0.w + c0.w + d0.w * u0.w;
            c1.x = r1.x + c1.x + d1.x * u1.x; c1.y = r1.y + c1.y + d1.y * u1.y;
            c1.z = r1.z + c1.z + d1.z * u1.z; c1.w = r1.w + c1.w + d1.w * u1.w;
        } else if (EPI == EPI_ADD) {
            float4 r0 = *reinterpret_cast<const float4*>(res + off);
            float4 r1 = *reinterpret_cast<const float4*>(res + off + 4);
            c0.x += r0.x; c0.y += r0.y; c0.z += r0.z; c0.w += r0.w;
            c1.x += r1.x; c1.y += r1.y; c1.z += r1.z; c1.w += r1.w;
        }
        *reinterpret_cast<float4*>(C + off)     = c0;
        *reinterpret_cast<float4*>(C + off + 4) = c1;
    }
}

// --------------------------- dual SwiGLU GEMM -------------------------------
// g[M,N] = silu(A@B0^T) * (A@B1^T). BM=128, BN=64, BK=16, 256 threads,
// 8x4 per thread per matrix. N need not be a multiple of 64 (guarded).
constexpr int BND = 64;

__global__ void __launch_bounds__(256)
gemm_dual_swiglu(const float* __restrict__ A, const float* __restrict__ B0,
                 const float* __restrict__ B1, float* __restrict__ C,
                 int M, int N, int K)
{
    __shared__ float As[BK][BM + 4];
    __shared__ float B0s[BK][BND + 4];
    __shared__ float B1s[BK][BND + 4];

    const int tid = threadIdx.x;
    const int mBase = blockIdx.y * BM;
    const int nBase = blockIdx.x * BND;
    const int tx = tid & 15;        // n: 4 cols at tx*4
    const int ty = tid >> 4;        // m: 8 rows at ty*8
    const int lr = tid >> 2;        // 0..63
    const int lq = tid & 3;

    const float* pa0 = A + (size_t)(mBase + lr)      * K + lq * 4;
    const float* pa1 = A + (size_t)(mBase + lr + 64) * K + lq * 4;
    const int brow = nBase + lr;
    const bool bok = (brow < N);
    const int browc = bok ? brow : 0;
    const float* pb0 = B0 + (size_t)browc * K + lq * 4;
    const float* pb1 = B1 + (size_t)browc * K + lq * 4;

    const float4 z4 = make_float4(0.f, 0.f, 0.f, 0.f);
    float4 ra0 = *reinterpret_cast<const float4*>(pa0);
    float4 ra1 = *reinterpret_cast<const float4*>(pa1);
    float4 rb0 = bok ? *reinterpret_cast<const float4*>(pb0) : z4;
    float4 rb1 = bok ? *reinterpret_cast<const float4*>(pb1) : z4;

    ull acc0[8][2], acc1[8][2];
    #pragma unroll
    for (int i = 0; i < 8; ++i) {
        acc0[i][0] = acc0[i][1] = 0ull;
        acc1[i][0] = acc1[i][1] = 0ull;
    }

    const int KT = K / BK;
    for (int kt = 0; kt < KT; ++kt) {
        As[lq*4+0][lr]      = ra0.x; As[lq*4+1][lr]      = ra0.y;
        As[lq*4+2][lr]      = ra0.z; As[lq*4+3][lr]      = ra0.w;
        As[lq*4+0][lr + 64] = ra1.x; As[lq*4+1][lr + 64] = ra1.y;
        As[lq*4+2][lr + 64] = ra1.z; As[lq*4+3][lr + 64] = ra1.w;
        B0s[lq*4+0][lr] = rb0.x; B0s[lq*4+1][lr] = rb0.y;
        B0s[lq*4+2][lr] = rb0.z; B0s[lq*4+3][lr] = rb0.w;
        B1s[lq*4+0][lr] = rb1.x; B1s[lq*4+1][lr] = rb1.y;
        B1s[lq*4+2][lr] = rb1.z; B1s[lq*4+3][lr] = rb1.w;
        __syncthreads();

        if (kt + 1 < KT) {
            ra0 = *reinterpret_cast<const float4*>(pa0 + (size_t)(kt + 1) * BK);
            ra1 = *reinterpret_cast<const float4*>(pa1 + (size_t)(kt + 1) * BK);
            rb0 = bok ? *reinterpret_cast<const float4*>(pb0 + (size_t)(kt + 1) * BK) : z4;
            rb1 = bok ? *reinterpret_cast<const float4*>(pb1 + (size_t)(kt + 1) * BK) : z4;
        }

        #pragma unroll
        for (int k = 0; k < BK; ++k) {
            float4 a0 = *reinterpret_cast<const float4*>(&As[k][ty * 8]);
            float4 a1 = *reinterpret_cast<const float4*>(&As[k][ty * 8 + 4]);
            ulonglong2 q0 = *reinterpret_cast<const ulonglong2*>(&B0s[k][tx * 4]);
            ulonglong2 q1 = *reinterpret_cast<const ulonglong2*>(&B1s[k][tx * 4]);
            ull aa[8] = {pack2(a0.x, a0.x), pack2(a0.y, a0.y),
                         pack2(a0.z, a0.z), pack2(a0.w, a0.w),
                         pack2(a1.x, a1.x), pack2(a1.y, a1.y),
                         pack2(a1.z, a1.z), pack2(a1.w, a1.w)};
            #pragma unroll
            for (int i = 0; i < 8; ++i) {
                acc0[i][0] = fma2(aa[i], q0.x, acc0[i][0]);
                acc0[i][1] = fma2(aa[i], q0.y, acc0[i][1]);
                acc1[i][0] = fma2(aa[i], q1.x, acc1[i][0]);
                acc1[i][1] = fma2(aa[i], q1.y, acc1[i][1]);
            }
        }
        __syncthreads();
    }

    // epilogue: silu(p0) * p1
    const int colb = nBase + tx * 4;
    #pragma unroll
    for (int i = 0; i < 8; ++i) {
        const int row = mBase + ty * 8 + i;
        const size_t off = (size_t)row * N + colb;
        float2 g0 = unpk(acc0[i][0]), g1 = unpk(acc0[i][1]);
        float2 v0 = unpk(acc1[i][0]), v1 = unpk(acc1[i][1]);
        float pg[4] = {g0.x, g0.y, g1.x, g1.y};
        float pv[4] = {v0.x, v0.y, v1.x, v1.y};
        float outv[4];
        #pragma unroll
        for (int j = 0; j < 4; ++j) {
            float a = pg[j];
            float s = a / (1.0f + __expf(-a));
            outv[j] = s * pv[j];
        }
        if (colb + 3 < N) {
            *reinterpret_cast<float4*>(C + off) =
                make_float4(outv[0], outv[1], outv[2], outv[3]);
        } else {
            #pragma unroll
            for (int j = 0; j < 4; ++j)
                if (colb + j < N) C[off + j] = outv[j];
        }
    }
}

// ------------------------------- launch ------------------------------------
extern "C" void kernel_launch(void* const* d_in, const int* in_sizes, int n_in,
                              void* d_out, int out_size)
{
    (void)in_sizes; (void)n_in; (void)out_size;
    const float* x        = (const float*)d_in[0];
    const float* log_lam  = (const float*)d_in[1];
    const float* B_w      = (const float*)d_in[2];
    const float* C_w      = (const float*)d_in[3];
    const float* D_skip   = (const float*)d_in[4];
    const float* ssm_w    = (const float*)d_in[5];
    const float* ffn_w    = (const float*)d_in[6];
    const float* w1       = (const float*)d_in[7];
    const float* w2       = (const float*)d_in[8];
    const float* w3       = (const float*)d_in[9];
    float* out = (float*)d_out;

    float *u, *Bu, *hs, *x1, *z, *g, *Hc, *Hs;
    cudaGetSymbolAddress((void**)&u,  g_u);
    cudaGetSymbolAddress((void**)&Bu, g_Bu);
    cudaGetSymbolAddress((void**)&hs, g_hs);
    cudaGetSymbolAddress((void**)&x1, g_x1);
    cudaGetSymbolAddress((void**)&z,  g_z);
    cudaGetSymbolAddress((void**)&g,  g_g);
    cudaGetSymbolAddress((void**)&Hc, g_Hc);
    cudaGetSymbolAddress((void**)&Hs, g_Hs);

    // 1) u = rmsnorm(x, ssm_norm_w)
    rmsnorm_kernel<<<MROWS, 256>>>(x, ssm_w, u);

    // 2) Bu = u @ B_w^T    [16384, 256]
    gemm_f32x2<EPI_NONE><<<dim3(NS / BN, MROWS / BM), 256>>>(
        u, B_w, Bu, MROWS, NS, DM, nullptr, nullptr, nullptr);

    // 3) chunked diagonal scan -> hs
    scan_local_kernel<<<B_SZ * NCHUNK, NS>>>(Bu, hs, Hc, log_lam);
    scan_carry_kernel<<<B_SZ, NS>>>(Hc, Hs, log_lam);
    scan_fix_kernel<<<B_SZ * NCHUNK, NS>>>(hs, Hs, log_lam);

    // 4) x1 = x + hs @ C_w^T + D_skip * u
    gemm_f32x2<EPI_SSM><<<dim3(DM / BN, MROWS / BM), 256>>>(
        hs, C_w, x1, MROWS, DM, NS, x, u, D_skip);

    // 5) z = rmsnorm(x1, ffn_norm_w)
    rmsnorm_kernel<<<MROWS, 256>>>(x1, ffn_w, z);

    // 6) g = silu(z @ w1^T) * (z @ w3^T)   [16384, 2736]
    gemm_dual_swiglu<<<dim3((DFF + BND - 1) / BND, MROWS / BM), 256>>>(
        z, w1, w3, g, MROWS, DFF, DM);

    // 7) out = x1 + g @ w2^T
    gemm_f32x2<EPI_ADD><<<dim3(DM / BN, MROWS / BM), 256>>>(
        g, w2, out, MROWS, DM, DFF, x1, nullptr, nullptr);
}

// round 2
// speedup vs baseline: 1.8630x; 1.8630x over previous
#include <cuda_runtime.h>
#include <cuda_bf16.h>
#include <cstdint>

#define DEV_INLINE __device__ __forceinline__

using bf16  = __nv_bfloat16;
using bf162 = __nv_bfloat162;

constexpr int B_SZ  = 4;
constexpr int T_LEN = 4096;
constexpr int DM    = 1024;
constexpr int NS    = 256;
constexpr int DFF   = 2736;
constexpr int DFFP  = 2752;            // DFF padded to /32 (and /64)
constexpr int MROWS = B_SZ * T_LEN;    // 16384
constexpr float EPSN = 1e-6f;

constexpr int CLEN   = 128;
constexpr int NCHUNK = T_LEN / CLEN;   // 32

// ------------------------------- scratch -----------------------------------
__device__ float g_u [(size_t)MROWS * DM];
__device__ float g_Bu[(size_t)MROWS * NS];
__device__ float g_hs[(size_t)MROWS * NS];
__device__ float g_x1[(size_t)MROWS * DM];
__device__ float g_zf[(size_t)MROWS * DM];
__device__ float g_Hc[B_SZ * NCHUNK * NS];
__device__ float g_Hs[B_SZ * NCHUNK * NS];

__device__ bf16 g_uh [(size_t)MROWS * DM];
__device__ bf16 g_ul [(size_t)MROWS * DM];
__device__ bf16 g_hsh[(size_t)MROWS * NS];
__device__ bf16 g_hsl[(size_t)MROWS * NS];
__device__ bf16 g_zh [(size_t)MROWS * DM];
__device__ bf16 g_zl [(size_t)MROWS * DM];
__device__ bf16 g_gh [(size_t)MROWS * DFFP];
__device__ bf16 g_gl [(size_t)MROWS * DFFP];

__device__ bf16 g_Bwh[NS * DM],  g_Bwl[NS * DM];
__device__ bf16 g_Cwh[DM * NS],  g_Cwl[DM * NS];
__device__ bf16 g_w1h[DFF * DM], g_w1l[DFF * DM];
__device__ bf16 g_w3h[DFF * DM], g_w3l[DFF * DM];
__device__ bf16 g_w2h[DM * DFFP], g_w2l[DM * DFFP];

// ------------------------------- PTX helpers -------------------------------
DEV_INLINE uint32_t s2u(const void* p) {
    return (uint32_t)__cvta_generic_to_shared(p);
}
DEV_INLINE void cpa16(uint32_t dst, const void* src, int sz) {
    asm volatile("cp.async.cg.shared.global [%0], [%1], 16, %2;\n"
                 :: "r"(dst), "l"(src), "r"(sz));
}
DEV_INLINE void cp_commit() { asm volatile("cp.async.commit_group;\n"); }
template <int N> DEV_INLINE void cp_wait() {
    asm volatile("cp.async.wait_group %0;\n" :: "n"(N));
}
DEV_INLINE void ldm4(uint32_t* r, uint32_t a) {
    asm volatile("ldmatrix.sync.aligned.m8n8.x4.shared.b16 {%0,%1,%2,%3}, [%4];\n"
                 : "=r"(r[0]), "=r"(r[1]), "=r"(r[2]), "=r"(r[3]) : "r"(a));
}
DEV_INLINE void mma16816(float* c, const uint32_t* a, const uint32_t* b) {
    asm volatile(
        "mma.sync.aligned.m16n8k16.row.col.f32.bf16.bf16.f32 "
        "{%0,%1,%2,%3}, {%4,%5,%6,%7}, {%8,%9}, {%0,%1,%2,%3};\n"
        : "+f"(c[0]), "+f"(c[1]), "+f"(c[2]), "+f"(c[3])
        : "r"(a[0]), "r"(a[1]), "r"(a[2]), "r"(a[3]), "r"(b[0]), "r"(b[1]));
}
DEV_INLINE void split1(float a, bf16& h, bf16& l) {
    h = __float2bfloat16(a);
    l = __float2bfloat16(a - __bfloat162float(h));
}

// ------------------------------- rmsnorm(+split) ---------------------------
__global__ void __launch_bounds__(256)
rmsnorm_split_kernel(const float* __restrict__ x, const float* __restrict__ w,
                     bf16* __restrict__ oh, bf16* __restrict__ ol,
                     float* __restrict__ of)
{
    const int row = blockIdx.x;
    const int tid = threadIdx.x;
    float4 v = reinterpret_cast<const float4*>(x + (size_t)row * DM)[tid];
    float ss = v.x*v.x + v.y*v.y + v.z*v.z + v.w*v.w;
    #pragma unroll
    for (int o = 16; o; o >>= 1) ss += __shfl_xor_sync(0xffffffffu, ss, o);
    __shared__ float red[8];
    if ((tid & 31) == 0) red[tid >> 5] = ss;
    __syncthreads();
    float tot = red[0]+red[1]+red[2]+red[3]+red[4]+red[5]+red[6]+red[7];
    float inv = rsqrtf(tot * (1.0f / (float)DM) + EPSN);
    float4 wv = reinterpret_cast<const float4*>(w)[tid];
    float o0 = v.x*inv*wv.x, o1 = v.y*inv*wv.y, o2 = v.z*inv*wv.z, o3 = v.w*inv*wv.w;
    reinterpret_cast<float4*>(of + (size_t)row * DM)[tid] = make_float4(o0,o1,o2,o3);
    bf16 h0,l0,h1,l1,h2,l2,h3,l3;
    split1(o0,h0,l0); split1(o1,h1,l1); split1(o2,h2,l2); split1(o3,h3,l3);
    bf162* ph = reinterpret_cast<bf162*>(oh + (size_t)row * DM);
    bf162* pl = reinterpret_cast<bf162*>(ol + (size_t)row * DM);
    ph[tid*2]   = bf162(h0,h1); ph[tid*2+1] = bf162(h2,h3);
    pl[tid*2]   = bf162(l0,l1); pl[tid*2+1] = bf162(l2,l3);
}

// ------------------------------- generic splits ----------------------------
__global__ void split_kernel(const float4* __restrict__ src,
                             bf162* __restrict__ h, bf162* __restrict__ l, int n4)
{
    int i = blockIdx.x * blockDim.x + threadIdx.x;
    if (i >= n4) return;
    float4 v = src[i];
    bf16 h0,l0,h1,l1,h2,l2,h3,l3;
    split1(v.x,h0,l0); split1(v.y,h1,l1); split1(v.z,h2,l2); split1(v.w,h3,l3);
    h[i*2]   = bf162(h0,h1); h[i*2+1] = bf162(h2,h3);
    l[i*2]   = bf162(l0,l1); l[i*2+1] = bf162(l2,l3);
}

__global__ void split_pad_kernel(const float* __restrict__ src,
                                 bf16* __restrict__ h, bf16* __restrict__ l,
                                 int rows, int K, int Kp)
{
    int i = blockIdx.x * blockDim.x + threadIdx.x;
    if (i >= rows * Kp) return;
    int r = i / Kp, c = i % Kp;
    float v = (c < K) ? src[(size_t)r * K + c] : 0.0f;
    bf16 hh, ll; split1(v, hh, ll);
    h[i] = hh; l[i] = ll;
}

// ------------------------------- scan (fp32) -------------------------------
DEV_INLINE float lam_of(const float* ll, int n) {
    return 1.0f / (1.0f + expf(-ll[n]));
}

__global__ void __launch_bounds__(NS)
scan_local_kernel(const float* __restrict__ Bu, float* __restrict__ hs,
                  float* __restrict__ Hc, const float* __restrict__ ll)
{
    const int bc = blockIdx.x, b = bc / NCHUNK, c = bc % NCHUNK, n = threadIdx.x;
    const float lam = lam_of(ll, n);
    size_t base = ((size_t)b * T_LEN + (size_t)c * CLEN) * NS + n;
    float h = 0.0f;
    #pragma unroll 4
    for (int i = 0; i < CLEN; ++i) {
        h = fmaf(lam, h, Bu[base + (size_t)i * NS]);
        hs[base + (size_t)i * NS] = h;
    }
    Hc[bc * NS + n] = h;
}

__global__ void __launch_bounds__(NS)
scan_carry_kernel(const float* __restrict__ Hc, float* __restrict__ Hs,
                  const float* __restrict__ ll)
{
    const int b = blockIdx.x, n = threadIdx.x;
    const float lam = lam_of(ll, n);
    float lamP = lam;
    #pragma unroll
    for (int j = 0; j < 7; ++j) lamP *= lamP;    // lam^128
    float h = 0.0f;
    for (int c = 0; c < NCHUNK; ++c) {
        Hs[(b * NCHUNK + c) * NS + n] = h;
        h = fmaf(lamP, h, Hc[(b * NCHUNK + c) * NS + n]);
    }
}

__global__ void __launch_bounds__(NS)
scan_fix_kernel(float* __restrict__ hs, const float* __restrict__ Hs,
                const float* __restrict__ ll)
{
    const int bc = blockIdx.x, b = bc / NCHUNK, c = bc % NCHUNK;
    if (c == 0) return;
    const int n = threadIdx.x;
    const float lam = lam_of(ll, n);
    const float h0 = Hs[bc * NS + n];
    size_t base = ((size_t)b * T_LEN + (size_t)c * CLEN) * NS + n;
    float p = lam;
    #pragma unroll 4
    for (int i = 0; i < CLEN; ++i) {
        size_t idx = base + (size_t)i * NS;
        hs[idx] = fmaf(p, h0, hs[idx]);
        p *= lam;
    }
}

// ----------------------- 3xBF16 tensor-core GEMM ---------------------------
// C[M,N] = A@B^T (fp32-equivalent via Ah·Bh + Al·Bh + Ah·Bl), BM=BN=128, BK=32.
// 8 warps (2x4), warp tile 64x32. Requires M%128==0, N%128==0, K%32==0.
constexpr int RSB   = 80;               // smem row stride bytes (32 bf16 + pad)
constexpr int TILE1 = 128 * RSB;        // 10240
constexpr int STG   = 4 * TILE1;        // Ah,Al,Bh,Bl per stage = 40960
constexpr int SMEM_GEMM = 2 * STG;      // 81920

enum { EPI_NONE = 0, EPI_SSM = 1, EPI_ADD = 2 };

template <int EPI>
__global__ void __launch_bounds__(256)
gemm3_kernel(const bf16* __restrict__ Ah, const bf16* __restrict__ Al,
             const bf16* __restrict__ Bh, const bf16* __restrict__ Bl,
             float* __restrict__ C, int M, int N, int K,
             const float* __restrict__ res, const float* __restrict__ uaux,
             const float* __restrict__ dskip)
{
    extern __shared__ char smem[];
    const uint32_t sb = s2u(smem);
    const int tid = threadIdx.x, lane = tid & 31, wid = tid >> 5;
    const int mBase = blockIdx.y * 128, nBase = blockIdx.x * 128;
    const int wm = wid >> 2, wn = wid & 3;

    // loader indexing: each thread loads row (tid>>1), chunks (tid&1)*2 + {0,1}
    const int lr = tid >> 1;
    const int lc = (tid & 1) * 2;
    const size_t aoff = (size_t)(mBase + lr) * K;
    const size_t boff = (size_t)(nBase + lr) * K;

    // ldmatrix lane addressing
    const int lrow = (lane & 7) | (((lane >> 3) & 1) << 3);
    const int lkb  = lane >> 4;

    float acc[4][4][4];
    #pragma unroll
    for (int i = 0; i < 4; ++i)
        #pragma unroll
        for (int j = 0; j < 4; ++j)
            #pragma unroll
            for (int q = 0; q < 4; ++q) acc[i][j][q] = 0.0f;

    const int KT = K / 32;

    auto LOAD = [&](int kt, int s) {
        uint32_t base = sb + s * STG;
        #pragma unroll
        for (int j = 0; j < 2; ++j) {
            int c = lc + j;
            uint32_t dst = base + lr * RSB + c * 16;
            const bf16* ga = Ah + aoff + kt * 32 + c * 8;
            const bf16* gl = Al + aoff + kt * 32 + c * 8;
            const bf16* gb = Bh + boff + kt * 32 + c * 8;
            const bf16* gd = Bl + boff + kt * 32 + c * 8;
            cpa16(dst,             ga, 16);
            cpa16(dst + TILE1,     gl, 16);
            cpa16(dst + 2*TILE1,   gb, 16);
            cpa16(dst + 3*TILE1,   gd, 16);
        }
        cp_commit();
    };

    LOAD(0, 0);

    for (int kt = 0; kt < KT; ++kt) {
        cp_wait<0>();
        __syncthreads();
        if (kt + 1 < KT) LOAD(kt + 1, (kt + 1) & 1);

        const uint32_t base = sb + (kt & 1) * STG;
        #pragma unroll
        for (int ss = 0; ss < 2; ++ss) {
            const uint32_t kofs = ss * 32;
            uint32_t afh[4][4], afl[4][4], bfh[4][2], bfl[4][2];
            #pragma unroll
            for (int mt = 0; mt < 4; ++mt) {
                uint32_t ad = base + (uint32_t)(wm*64 + mt*16 + lrow) * RSB
                            + kofs + lkb * 16;
                ldm4(afh[mt], ad);
                ldm4(afl[mt], ad + TILE1);
            }
            #pragma unroll
            for (int p = 0; p < 2; ++p) {
                uint32_t bd = base + 2*TILE1
                            + (uint32_t)(wn*32 + p*16 + lrow) * RSB
                            + kofs + lkb * 16;
                uint32_t r[4];
                ldm4(r, bd);
                bfh[2*p][0] = r[0]; bfh[2*p][1] = r[2];
                bfh[2*p+1][0] = r[1]; bfh[2*p+1][1] = r[3];
                ldm4(r, bd + TILE1);
                bfl[2*p][0] = r[0]; bfl[2*p][1] = r[2];
                bfl[2*p+1][0] = r[1]; bfl[2*p+1][1] = r[3];
            }
            #pragma unroll
            for (int mt = 0; mt < 4; ++mt)
                #pragma unroll
                for (int nt = 0; nt < 4; ++nt) {
                    mma16816(acc[mt][nt], afh[mt], bfh[nt]);
                    mma16816(acc[mt][nt], afl[mt], bfh[nt]);
                    mma16816(acc[mt][nt], afh[mt], bfl[nt]);
                }
        }
        __syncthreads();
    }

    // epilogue
    const int g = lane >> 2, t = lane & 3;
    #pragma unroll
    for (int mt = 0; mt < 4; ++mt) {
        #pragma unroll
        for (int nt = 0; nt < 4; ++nt) {
            const int col  = nBase + wn*32 + nt*8 + t*2;
            const int row0 = mBase + wm*64 + mt*16 + g;
            const int row1 = row0 + 8;
            float2 v0 = make_float2(acc[mt][nt][0], acc[mt][nt][1]);
            float2 v1 = make_float2(acc[mt][nt][2], acc[mt][nt][3]);
            const size_t o0 = (size_t)row0 * N + col;
            const size_t o1 = (size_t)row1 * N + col;
            if (EPI == EPI_SSM) {
                float2 d  = *reinterpret_cast<const float2*>(dskip + col);
                float2 r0 = *reinterpret_cast<const float2*>(res + o0);
                float2 r1 = *reinterpret_cast<const float2*>(res + o1);
                float2 u0 = *reinterpret_cast<const float2*>(uaux + o0);
                float2 u1 = *reinterpret_cast<const float2*>(uaux + o1);
                v0.x = r0.x + v0.x + d.x * u0.x; v0.y = r0.y + v0.y + d.y * u0.y;
                v1.x = r1.x + v1.x + d.x * u1.x; v1.y = r1.y + v1.y + d.y * u1.y;
            } else if (EPI == EPI_ADD) {
                float2 r0 = *reinterpret_cast<const float2*>(res + o0);
                float2 r1 = *reinterpret_cast<const float2*>(res + o1);
                v0.x += r0.x; v0.y += r0.y;
                v1.x += r1.x; v1.y += r1.y;
            }
            *reinterpret_cast<float2*>(C + o0) = v0;
            *reinterpret_cast<float2*>(C + o1) = v1;
        }
    }
}

// ------------------- dual SwiGLU 3xBF16 GEMM (BN=64) ------------------------
// gate = A@W1^T, val = A@W3^T; out = split(silu(gate)*val) -> (gh, gl), stride Kp.
constexpr int TILB1 = 64 * RSB;                 // 5120
constexpr int STG_D = 2 * TILE1 + 4 * TILB1;    // 40960
constexpr int SMEM_DUAL = 2 * STG_D;            // 81920

__global__ void __launch_bounds__(256)
swiglu_kernel(const bf16* __restrict__ Ah, const bf16* __restrict__ Al,
              const bf16* __restrict__ W1h, const bf16* __restrict__ W1l,
              const bf16* __restrict__ W3h, const bf16* __restrict__ W3l,
              bf16* __restrict__ Gh, bf16* __restrict__ Gl,
              int M, int N, int Kp, int K)
{
    extern __shared__ char smem[];
    const uint32_t sb = s2u(smem);
    const int tid = threadIdx.x, lane = tid & 31, wid = tid >> 5;
    const int mBase = blockIdx.y * 128, nBase = blockIdx.x * 64;
    const int wm = wid >> 2, wn = wid & 3;

    const int lra = tid >> 1, lca = (tid & 1) * 2;    // A loader
    const int lrb = tid >> 2, lcb = tid & 3;          // B loader
    const size_t aoff = (size_t)(mBase + lra) * K;
    const int nrow = nBase + lrb;
    const bool bok = nrow < N;
    const size_t boff = (size_t)(bok ? nrow : 0) * K;
    const int bsz = bok ? 16 : 0;

    const int lrow = (lane & 7) | (((lane >> 3) & 1) << 3);
    const int lkb  = lane >> 4;

    float accG[4][2][4], accV[4][2][4];
    #pragma unroll
    for (int i = 0; i < 4; ++i)
        #pragma unroll
        for (int j = 0; j < 2; ++j)
            #pragma unroll
            for (int q = 0; q < 4; ++q) { accG[i][j][q] = 0.0f; accV[i][j][q] = 0.0f; }

    const int KT = K / 32;

    auto LOAD = [&](int kt, int s) {
        uint32_t base = sb + s * STG_D;
        #pragma unroll
        for (int j = 0; j < 2; ++j) {
            int c = lca + j;
            uint32_t dst = base + lra * RSB + c * 16;
            cpa16(dst,         Ah + aoff + kt * 32 + c * 8, 16);
            cpa16(dst + TILE1, Al + aoff + kt * 32 + c * 8, 16);
        }
        {
            uint32_t dst = base + 2*TILE1 + lrb * RSB + lcb * 16;
            const size_t go = boff + kt * 32 + lcb * 8;
            cpa16(dst,             W1h + go, bsz);
            cpa16(dst + TILB1,     W1l + go, bsz);
            cpa16(dst + 2*TILB1,   W3h + go, bsz);
            cpa16(dst + 3*TILB1,   W3l + go, bsz);
        }
        cp_commit();
    };

    LOAD(0, 0);

    for (int kt = 0; kt < KT; ++kt) {
        cp_wait<0>();
        __syncthreads();
        if (kt + 1 < KT) LOAD(kt + 1, (kt + 1) & 1);

        const uint32_t base = sb + (kt & 1) * STG_D;
        #pragma unroll
        for (int ss = 0; ss < 2; ++ss) {
            const uint32_t kofs = ss * 32;
            uint32_t afh[4][4], afl[4][4];
            uint32_t b1h[2][2], b1l[2][2], b3h[2][2], b3l[2][2];
            #pragma unroll
            for (int mt = 0; mt < 4; ++mt) {
                uint32_t ad = base + (uint32_t)(wm*64 + mt*16 + lrow) * RSB
                            + kofs + lkb * 16;
                ldm4(afh[mt], ad);
                ldm4(afl[mt], ad + TILE1);
            }
            {
                uint32_t bd = base + 2*TILE1
                            + (uint32_t)(wn*16 + lrow) * RSB + kofs + lkb * 16;
                uint32_t r[4];
                ldm4(r, bd);
                b1h[0][0]=r[0]; b1h[0][1]=r[2]; b1h[1][0]=r[1]; b1h[1][1]=r[3];
                ldm4(r, bd + TILB1);
                b1l[0][0]=r[0]; b1l[0][1]=r[2]; b1l[1][0]=r[1]; b1l[1][1]=r[3];
                ldm4(r, bd + 2*TILB1);
                b3h[0][0]=r[0]; b3h[0][1]=r[2]; b3h[1][0]=r[1]; b3h[1][1]=r[3];
                ldm4(r, bd + 3*TILB1);
                b3l[0][0]=r[0]; b3l[0][1]=r[2]; b3l[1][0]=r[1]; b3l[1][1]=r[3];
            }
            #pragma unroll
            for (int mt = 0; mt < 4; ++mt)
                #pragma unroll
                for (int nt = 0; nt < 2; ++nt) {
                    mma16816(accG[mt][nt], afh[mt], b1h[nt]);
                    mma16816(accG[mt][nt], afl[mt], b1h[nt]);
                    mma16816(accG[mt][nt], afh[mt], b1l[nt]);
                    mma16816(accV[mt][nt], afh[mt], b3h[nt]);
                    mma16816(accV[mt][nt], afl[mt], b3h[nt]);
                    mma16816(accV[mt][nt], afh[mt], b3l[nt]);
                }
        }
        __syncthreads();
    }

    // epilogue: o = silu(gate) * val, split to (h, l) bf16, strided Kp
    const int g = lane >> 2, t = lane & 3;
    #pragma unroll
    for (int mt = 0; mt < 4; ++mt) {
        #pragma unroll
        for (int nt = 0; nt < 2; ++nt) {
            const int col  = nBase + wn*16 + nt*8 + t*2;
            const int row0 = mBase + wm*64 + mt*16 + g;
            #pragma unroll
            for (int half = 0; half < 2; ++half) {
                const int row = row0 + half * 8;
                float gg0 = accG[mt][nt][half*2],   gg1 = accG[mt][nt][half*2+1];
                float vv0 = accV[mt][nt][half*2],   vv1 = accV[mt][nt][half*2+1];
                float o0 = gg0 / (1.0f + __expf(-gg0)) * vv0;
                float o1 = gg1 / (1.0f + __expf(-gg1)) * vv1;
                bf16 h0,l0,h1,l1;
                split1(o0,h0,l0); split1(o1,h1,l1);
                const size_t off = (size_t)row * Kp + col;
                *reinterpret_cast<bf162*>(Gh + off) = bf162(h0,h1);
                *reinterpret_cast<bf162*>(Gl + off) = bf162(l0,l1);
            }
        }
    }
}

// ------------------------------- launch -------------------------------------
extern "C" void kernel_launch(void* const* d_in, const int* in_sizes, int n_in,
                              void* d_out, int out_size)
{
    (void)in_sizes; (void)n_in; (void)out_size;
    const float* x        = (const float*)d_in[0];
    const float* log_lam  = (const float*)d_in[1];
    const float* B_w      = (const float*)d_in[2];
    const float* C_w      = (const float*)d_in[3];
    const float* D_skip   = (const float*)d_in[4];
    const float* ssm_w    = (const float*)d_in[5];
    const float* ffn_w    = (const float*)d_in[6];
    const float* w1       = (const float*)d_in[7];
    const float* w2       = (const float*)d_in[8];
    const float* w3       = (const float*)d_in[9];
    float* out = (float*)d_out;

    cudaFuncSetAttribute(gemm3_kernel<EPI_NONE>,
        cudaFuncAttributeMaxDynamicSharedMemorySize, SMEM_GEMM);
    cudaFuncSetAttribute(gemm3_kernel<EPI_SSM>,
        cudaFuncAttributeMaxDynamicSharedMemorySize, SMEM_GEMM);
    cudaFuncSetAttribute(gemm3_kernel<EPI_ADD>,
        cudaFuncAttributeMaxDynamicSharedMemorySize, SMEM_GEMM);
    cudaFuncSetAttribute(swiglu_kernel,
        cudaFuncAttributeMaxDynamicSharedMemorySize, SMEM_DUAL);

    float *u, *Bu, *hs, *x1, *zf, *Hc, *Hs;
    bf16 *uh, *ul, *hsh, *hsl, *zh, *zl, *gh, *gl;
    bf16 *Bwh, *Bwl, *Cwh, *Cwl, *w1h, *w1l, *w3h, *w3l, *w2h, *w2l;
    cudaGetSymbolAddress((void**)&u,   g_u);
    cudaGetSymbolAddress((void**)&Bu,  g_Bu);
    cudaGetSymbolAddress((void**)&hs,  g_hs);
    cudaGetSymbolAddress((void**)&x1,  g_x1);
    cudaGetSymbolAddress((void**)&zf,  g_zf);
    cudaGetSymbolAddress((void**)&Hc,  g_Hc);
    cudaGetSymbolAddress((void**)&Hs,  g_Hs);
    cudaGetSymbolAddress((void**)&uh,  g_uh);
    cudaGetSymbolAddress((void**)&ul,  g_ul);
    cudaGetSymbolAddress((void**)&hsh, g_hsh);
    cudaGetSymbolAddress((void**)&hsl, g_hsl);
    cudaGetSymbolAddress((void**)&zh,  g_zh);
    cudaGetSymbolAddress((void**)&zl,  g_zl);
    cudaGetSymbolAddress((void**)&gh,  g_gh);
    cudaGetSymbolAddress((void**)&gl,  g_gl);
    cudaGetSymbolAddress((void**)&Bwh, g_Bwh);
    cudaGetSymbolAddress((void**)&Bwl, g_Bwl);
    cudaGetSymbolAddress((void**)&Cwh, g_Cwh);
    cudaGetSymbolAddress((void**)&Cwl, g_Cwl);
    cudaGetSymbolAddress((void**)&w1h, g_w1h);
    cudaGetSymbolAddress((void**)&w1l, g_w1l);
    cudaGetSymbolAddress((void**)&w3h, g_w3h);
    cudaGetSymbolAddress((void**)&w3l, g_w3l);
    cudaGetSymbolAddress((void**)&w2h, g_w2h);
    cudaGetSymbolAddress((void**)&w2l, g_w2l);

    // weight splits
    {
        int n4 = NS * DM / 4;
        split_kernel<<<(n4 + 255)/256, 256>>>((const float4*)B_w, (bf162*)Bwh, (bf162*)Bwl, n4);
        n4 = DM * NS / 4;
        split_kernel<<<(n4 + 255)/256, 256>>>((const float4*)C_w, (bf162*)Cwh, (bf162*)Cwl, n4);
        n4 = DFF * DM / 4;
        split_kernel<<<(n4 + 255)/256, 256>>>((const float4*)w1, (bf162*)w1h, (bf162*)w1l, n4);
        split_kernel<<<(n4 + 255)/256, 256>>>((const float4*)w3, (bf162*)w3h, (bf162*)w3l, n4);
        int np = DM * DFFP;
        split_pad_kernel<<<(np + 255)/256, 256>>>(w2, w2h, w2l, DM, DFF, DFFP);
    }

    // 1) u = rmsnorm(x, ssm_norm_w)  (fp32 + bf16 split)
    rmsnorm_split_kernel<<<MROWS, 256>>>(x, ssm_w, uh, ul, u);

    // 2) Bu = u @ B_w^T  [16384, 256], K=1024
    gemm3_kernel<EPI_NONE><<<dim3(NS/128, MROWS/128), 256, SMEM_GEMM>>>(
        uh, ul, Bwh, Bwl, Bu, MROWS, NS, DM, nullptr, nullptr, nullptr);

    // 3) chunked diagonal scan -> hs (fp32)
    scan_local_kernel<<<B_SZ * NCHUNK, NS>>>(Bu, hs, Hc, log_lam);
    scan_carry_kernel<<<B_SZ, NS>>>(Hc, Hs, log_lam);
    scan_fix_kernel<<<B_SZ * NCHUNK, NS>>>(hs, Hs, log_lam);

    // 3b) split hs
    {
        int n4 = MROWS * NS / 4;
        split_kernel<<<(n4 + 255)/256, 256>>>((const float4*)hs, (bf162*)hsh, (bf162*)hsl, n4);
    }

    // 4) x1 = x + hs @ C_w^T + D_skip * u  [16384, 1024], K=256
    gemm3_kernel<EPI_SSM><<<dim3(DM/128, MROWS/128), 256, SMEM_GEMM>>>(
        hsh, hsl, Cwh, Cwl, x1, MROWS, DM, NS, x, u, D_skip);

    // 5) z = rmsnorm(x1, ffn_norm_w) (split bf16)
    rmsnorm_split_kernel<<<MROWS, 256>>>(x1, ffn_w, zh, zl, zf);

    // 6) g = split(silu(z@w1^T) * (z@w3^T))  [16384, 2752-padded], K=1024
    swiglu_kernel<<<dim3(DFFP/64, MROWS/128), 256, SMEM_DUAL>>>(
        zh, zl, w1h, w1l, w3h, w3l, gh, gl, MROWS, DFF, DFFP, DM);

    // 7) out = x1 + g @ w2^T  [16384, 1024], K=2752
    gemm3_kernel<EPI_ADD><<<dim3(DM/128, MROWS/128), 256, SMEM_GEMM>>>(
        gh, gl, w2h, w2l, out, MROWS, DM, DFFP, x1, nullptr, nullptr);
}

// round 4
// speedup vs baseline: 2.5435x; 1.3652x over previous
#include <cuda_runtime.h>
#include <cuda_fp16.h>
#include <cstdint>

#define DEV_INLINE __device__ __forceinline__

using f16 = __half;

constexpr int B_SZ  = 4;
constexpr int T_LEN = 4096;
constexpr int DM    = 1024;
constexpr int NS    = 256;
constexpr int DFF   = 2736;
constexpr int DFFP  = 2752;            // padded to /64
constexpr int MROWS = B_SZ * T_LEN;    // 16384
constexpr float EPSN = 1e-6f;

constexpr int CLEN   = 128;
constexpr int NCHUNK = T_LEN / CLEN;   // 32

// ------------------------------- scratch -----------------------------------
__device__ float g_u [(size_t)MROWS * DM];
__device__ float g_Bu[(size_t)MROWS * NS];
__device__ float g_hs[(size_t)MROWS * NS];
__device__ float g_x1[(size_t)MROWS * DM];
__device__ float g_Hc[B_SZ * NCHUNK * NS];
__device__ float g_Hs[B_SZ * NCHUNK * NS];

__device__ f16 g_uh [(size_t)MROWS * DM];
__device__ f16 g_ul [(size_t)MROWS * DM];
__device__ f16 g_hsh[(size_t)MROWS * NS];
__device__ f16 g_hsl[(size_t)MROWS * NS];
__device__ f16 g_zh [(size_t)MROWS * DM];
__device__ f16 g_zl [(size_t)MROWS * DM];
__device__ f16 g_gh [(size_t)MROWS * DFFP];
__device__ f16 g_gl [(size_t)MROWS * DFFP];

// fp16 weights (single copy; padded tails zero)
__device__ f16 g_Bw16[NS * DM];
__device__ f16 g_Cw16[DM * NS];
__device__ f16 g_w116[DFFP * DM];
__device__ f16 g_w316[DFFP * DM];
__device__ f16 g_w216[DM * DFFP];

// ------------------------------- PTX helpers -------------------------------
DEV_INLINE uint32_t s2u(const void* p) {
    return (uint32_t)__cvta_generic_to_shared(p);
}
DEV_INLINE void cpa16(uint32_t dst, const void* src) {
    asm volatile("cp.async.cg.shared.global [%0], [%1], 16;\n"
                 :: "r"(dst), "l"(src));
}
DEV_INLINE void cp_commit() { asm volatile("cp.async.commit_group;\n"); }
template <int N> DEV_INLINE void cp_wait() {
    asm volatile("cp.async.wait_group %0;\n" :: "n"(N));
}
DEV_INLINE void ldm4(uint32_t* r, uint32_t a) {
    asm volatile("ldmatrix.sync.aligned.m8n8.x4.shared.b16 {%0,%1,%2,%3}, [%4];\n"
                 : "=r"(r[0]), "=r"(r[1]), "=r"(r[2]), "=r"(r[3]) : "r"(a));
}
DEV_INLINE void mma16816(float* c, const uint32_t* a, const uint32_t* b) {
    asm volatile(
        "mma.sync.aligned.m16n8k16.row.col.f32.f16.f16.f32 "
        "{%0,%1,%2,%3}, {%4,%5,%6,%7}, {%8,%9}, {%0,%1,%2,%3};\n"
        : "+f"(c[0]), "+f"(c[1]), "+f"(c[2]), "+f"(c[3])
        : "r"(a[0]), "r"(a[1]), "r"(a[2]), "r"(a[3]), "r"(b[0]), "r"(b[1]));
}
DEV_INLINE void split1(float a, f16& h, f16& l) {
    h = __float2half_rn(a);
    l = __float2half_rn(a - __half2float(h));
}

// ------------------------------- rmsnorm(+split) ---------------------------
__global__ void __launch_bounds__(256)
rmsnorm_split_kernel(const float* __restrict__ x, const float* __restrict__ w,
                     f16* __restrict__ oh, f16* __restrict__ ol,
                     float* __restrict__ of)
{
    const int row = blockIdx.x;
    const int tid = threadIdx.x;
    float4 v = reinterpret_cast<const float4*>(x + (size_t)row * DM)[tid];
    float ss = v.x*v.x + v.y*v.y + v.z*v.z + v.w*v.w;
    #pragma unroll
    for (int o = 16; o; o >>= 1) ss += __shfl_xor_sync(0xffffffffu, ss, o);
    __shared__ float red[8];
    if ((tid & 31) == 0) red[tid >> 5] = ss;
    __syncthreads();
    float tot = red[0]+red[1]+red[2]+red[3]+red[4]+red[5]+red[6]+red[7];
    float inv = rsqrtf(tot * (1.0f / (float)DM) + EPSN);
    float4 wv = reinterpret_cast<const float4*>(w)[tid];
    float o0 = v.x*inv*wv.x, o1 = v.y*inv*wv.y, o2 = v.z*inv*wv.z, o3 = v.w*inv*wv.w;
    if (of)
        reinterpret_cast<float4*>(of + (size_t)row * DM)[tid] = make_float4(o0,o1,o2,o3);
    f16 h0,l0,h1,l1,h2,l2,h3,l3;
    split1(o0,h0,l0); split1(o1,h1,l1); split1(o2,h2,l2); split1(o3,h3,l3);
    __half2* ph = reinterpret_cast<__half2*>(oh + (size_t)row * DM);
    __half2* pl = reinterpret_cast<__half2*>(ol + (size_t)row * DM);
    ph[tid*2]   = __half2(h0,h1); ph[tid*2+1] = __half2(h2,h3);
    pl[tid*2]   = __half2(l0,l1); pl[tid*2+1] = __half2(l2,l3);
}

// --------------------------- weight conversions ----------------------------
__global__ void conv_kernel(const float4* __restrict__ src,
                            __half2* __restrict__ dst, int n4)
{
    int i = blockIdx.x * blockDim.x + threadIdx.x;
    if (i >= n4) return;
    float4 v = src[i];
    dst[i*2]   = __half2(__float2half_rn(v.x), __float2half_rn(v.y));
    dst[i*2+1] = __half2(__float2half_rn(v.z), __float2half_rn(v.w));
}

// pad rows: dst[DFFP][DM], src[DFF][DM]
__global__ void conv_padrow_kernel(const float* __restrict__ src,
                                   f16* __restrict__ dst, int rows, int rowsP, int cols)
{
    int i = blockIdx.x * blockDim.x + threadIdx.x;
    if (i >= rowsP * cols) return;
    int r = i / cols;
    dst[i] = __float2half_rn(r < rows ? src[(size_t)r * cols + (i % cols)] : 0.0f);
}

// pad cols: dst[DM][DFFP], src[DM][DFF]
__global__ void conv_padcol_kernel(const float* __restrict__ src,
                                   f16* __restrict__ dst, int rows, int K, int Kp)
{
    int i = blockIdx.x * blockDim.x + threadIdx.x;
    if (i >= rows * Kp) return;
    int r = i / Kp, c = i % Kp;
    dst[i] = __float2half_rn(c < K ? src[(size_t)r * K + c] : 0.0f);
}

// ------------------------------- scan (fp32) -------------------------------
DEV_INLINE float lam_of(const float* ll, int n) {
    return 1.0f / (1.0f + expf(-ll[n]));
}

__global__ void __launch_bounds__(NS)
scan_local_kernel(const float* __restrict__ Bu, float* __restrict__ hs,
                  float* __restrict__ Hc, const float* __restrict__ ll)
{
    const int bc = blockIdx.x, b = bc / NCHUNK, c = bc % NCHUNK, n = threadIdx.x;
    const float lam = lam_of(ll, n);
    size_t base = ((size_t)b * T_LEN + (size_t)c * CLEN) * NS + n;
    float h = 0.0f;
    #pragma unroll 4
    for (int i = 0; i < CLEN; ++i) {
        h = fmaf(lam, h, Bu[base + (size_t)i * NS]);
        hs[base + (size_t)i * NS] = h;
    }
    Hc[bc * NS + n] = h;
}

__global__ void __launch_bounds__(NS)
scan_carry_kernel(const float* __restrict__ Hc, float* __restrict__ Hs,
                  const float* __restrict__ ll)
{
    const int b = blockIdx.x, n = threadIdx.x;
    const float lam = lam_of(ll, n);
    float lamP = lam;
    #pragma unroll
    for (int j = 0; j < 7; ++j) lamP *= lamP;    // lam^128
    float h = 0.0f;
    for (int c = 0; c < NCHUNK; ++c) {
        Hs[(b * NCHUNK + c) * NS + n] = h;
        h = fmaf(lamP, h, Hc[(b * NCHUNK + c) * NS + n]);
    }
}

// fixup + fp16 h/l split fused
__global__ void __launch_bounds__(NS)
scan_fix_split_kernel(const float* __restrict__ hs, const float* __restrict__ Hs,
                      const float* __restrict__ ll,
                      f16* __restrict__ oh, f16* __restrict__ ol)
{
    const int bc = blockIdx.x, b = bc / NCHUNK, c = bc % NCHUNK;
    const int n = threadIdx.x;
    const float lam = lam_of(ll, n);
    const float h0 = Hs[bc * NS + n];
    size_t base = ((size_t)b * T_LEN + (size_t)c * CLEN) * NS + n;
    float p = lam;
    #pragma unroll 4
    for (int i = 0; i < CLEN; ++i) {
        size_t idx = base + (size_t)i * NS;
        float v = (c == 0) ? hs[idx] : fmaf(p, h0, hs[idx]);
        f16 hh, llo; split1(v, hh, llo);
        oh[idx] = hh; ol[idx] = llo;
        p *= lam;
    }
}

// ----------------------- 2-term fp16 tensor-core GEMM ----------------------
// C[M,N] = A@B^T via Ah·B16 + Al·B16, fp32 accum. BM=BN=128, BK=32,
// 8 warps (2x4), warp tile 64x32. M%128==0, N%128==0, K%32==0.
constexpr int RSB   = 80;               // smem row stride bytes (32 f16 + pad)
constexpr int TILE1 = 128 * RSB;        // 10240
constexpr int STG   = 3 * TILE1;        // Ah,Al,B = 30720
constexpr int SMEM_GEMM = 2 * STG;      // 61440

enum { EPI_NONE = 0, EPI_SSM = 1, EPI_ADD = 2 };

template <int EPI>
__global__ void __launch_bounds__(256)
gemm2_kernel(const f16* __restrict__ Ah, const f16* __restrict__ Al,
             const f16* __restrict__ Bw, float* __restrict__ C,
             int M, int N, int K,
             const float* __restrict__ res, const float* __restrict__ uaux,
             const float* __restrict__ dskip)
{
    extern __shared__ char smem[];
    const uint32_t sb = s2u(smem);
    const int tid = threadIdx.x, lane = tid & 31, wid = tid >> 5;
    const int mBase = blockIdx.y * 128, nBase = blockIdx.x * 128;
    const int wm = wid >> 2, wn = wid & 3;

    const int lr = tid >> 1;
    const int lc = (tid & 1) * 2;
    const size_t aoff = (size_t)(mBase + lr) * K;
    const size_t boff = (size_t)(nBase + lr) * K;

    const int lrow = (lane & 7) | (((lane >> 3) & 1) << 3);
    const int lkb  = lane >> 4;

    float acc[4][4][4];
    #pragma unroll
    for (int i = 0; i < 4; ++i)
        #pragma unroll
        for (int j = 0; j < 4; ++j)
            #pragma unroll
            for (int q = 0; q < 4; ++q) acc[i][j][q] = 0.0f;

    const int KT = K / 32;

    auto LOAD = [&](int kt, int s) {
        uint32_t base = sb + s * STG;
        #pragma unroll
        for (int j = 0; j < 2; ++j) {
            int c = lc + j;
            uint32_t dst = base + lr * RSB + c * 16;
            cpa16(dst,           Ah + aoff + kt * 32 + c * 8);
            cpa16(dst + TILE1,   Al + aoff + kt * 32 + c * 8);
            cpa16(dst + 2*TILE1, Bw + boff + kt * 32 + c * 8);
        }
        cp_commit();
    };

    LOAD(0, 0);

    for (int kt = 0; kt < KT; ++kt) {
        cp_wait<0>();
        __syncthreads();
        if (kt + 1 < KT) LOAD(kt + 1, (kt + 1) & 1);

        const uint32_t base = sb + (kt & 1) * STG;
        #pragma unroll
        for (int ss = 0; ss < 2; ++ss) {
            const uint32_t kofs = ss * 32;
            uint32_t afh[4][4], afl[4][4], bf[4][2];
            #pragma unroll
            for (int mt = 0; mt < 4; ++mt) {
                uint32_t ad = base + (uint32_t)(wm*64 + mt*16 + lrow) * RSB
                            + kofs + lkb * 16;
                ldm4(afh[mt], ad);
                ldm4(afl[mt], ad + TILE1);
            }
            #pragma unroll
            for (int p = 0; p < 2; ++p) {
                uint32_t bd = base + 2*TILE1
                            + (uint32_t)(wn*32 + p*16 + lrow) * RSB
                            + kofs + lkb * 16;
                uint32_t r[4];
                ldm4(r, bd);
                bf[2*p][0]   = r[0]; bf[2*p][1]   = r[2];
                bf[2*p+1][0] = r[1]; bf[2*p+1][1] = r[3];
            }
            #pragma unroll
            for (int mt = 0; mt < 4; ++mt)
                #pragma unroll
                for (int nt = 0; nt < 4; ++nt) {
                    mma16816(acc[mt][nt], afh[mt], bf[nt]);
                    mma16816(acc[mt][nt], afl[mt], bf[nt]);
                }
        }
        __syncthreads();
    }

    // epilogue
    const int g = lane >> 2, t = lane & 3;
    #pragma unroll
    for (int mt = 0; mt < 4; ++mt) {
        #pragma unroll
        for (int nt = 0; nt < 4; ++nt) {
            const int col  = nBase + wn*32 + nt*8 + t*2;
            const int row0 = mBase + wm*64 + mt*16 + g;
            const int row1 = row0 + 8;
            float2 v0 = make_float2(acc[mt][nt][0], acc[mt][nt][1]);
            float2 v1 = make_float2(acc[mt][nt][2], acc[mt][nt][3]);
            const size_t o0 = (size_t)row0 * N + col;
            const size_t o1 = (size_t)row1 * N + col;
            if (EPI == EPI_SSM) {
                float2 d  = *reinterpret_cast<const float2*>(dskip + col);
                float2 r0 = *reinterpret_cast<const float2*>(res + o0);
                float2 r1 = *reinterpret_cast<const float2*>(res + o1);
                float2 u0 = *reinterpret_cast<const float2*>(uaux + o0);
                float2 u1 = *reinterpret_cast<const float2*>(uaux + o1);
                v0.x = r0.x + v0.x + d.x * u0.x; v0.y = r0.y + v0.y + d.y * u0.y;
                v1.x = r1.x + v1.x + d.x * u1.x; v1.y = r1.y + v1.y + d.y * u1.y;
            } else if (EPI == EPI_ADD) {
                float2 r0 = *reinterpret_cast<const float2*>(res + o0);
                float2 r1 = *reinterpret_cast<const float2*>(res + o1);
                v0.x += r0.x; v0.y += r0.y;
                v1.x += r1.x; v1.y += r1.y;
            }
            *reinterpret_cast<float2*>(C + o0) = v0;
            *reinterpret_cast<float2*>(C + o1) = v1;
        }
    }
}

// ------------------- dual SwiGLU 2-term fp16 GEMM (BN=64) -------------------
constexpr int TILB1 = 64 * RSB;                 // 5120
constexpr int STG_D = 2 * TILE1 + 2 * TILB1;    // 30720
constexpr int SMEM_DUAL = 2 * STG_D;            // 61440

__global__ void __launch_bounds__(256)
swiglu_kernel(const f16* __restrict__ Ah, const f16* __restrict__ Al,
              const f16* __restrict__ W1, const f16* __restrict__ W3,
              f16* __restrict__ Gh, f16* __restrict__ Gl,
              int M, int Kp, int K)
{
    extern __shared__ char smem[];
    const uint32_t sb = s2u(smem);
    const int tid = threadIdx.x, lane = tid & 31, wid = tid >> 5;
    const int mBase = blockIdx.y * 128, nBase = blockIdx.x * 64;
    const int wm = wid >> 2, wn = wid & 3;

    const int lra = tid >> 1, lca = (tid & 1) * 2;    // A loader
    const int lrb = tid >> 2, lcb = tid & 3;          // B loader
    const size_t aoff = (size_t)(mBase + lra) * K;
    const size_t boff = (size_t)(nBase + lrb) * K;    // weights padded: no guard

    const int lrow = (lane & 7) | (((lane >> 3) & 1) << 3);
    const int lkb  = lane >> 4;

    float accG[4][2][4], accV[4][2][4];
    #pragma unroll
    for (int i = 0; i < 4; ++i)
        #pragma unroll
        for (int j = 0; j < 2; ++j)
            #pragma unroll
            for (int q = 0; q < 4; ++q) { accG[i][j][q] = 0.0f; accV[i][j][q] = 0.0f; }

    const int KT = K / 32;

    auto LOAD = [&](int kt, int s) {
        uint32_t base = sb + s * STG_D;
        #pragma unroll
        for (int j = 0; j < 2; ++j) {
            int c = lca + j;
            uint32_t dst = base + lra * RSB + c * 16;
            cpa16(dst,         Ah + aoff + kt * 32 + c * 8);
            cpa16(dst + TILE1, Al + aoff + kt * 32 + c * 8);
        }
        {
            uint32_t dst = base + 2*TILE1 + lrb * RSB + lcb * 16;
            const size_t go = boff + kt * 32 + lcb * 8;
            cpa16(dst,         W1 + go);
            cpa16(dst + TILB1, W3 + go);
        }
        cp_commit();
    };

    LOAD(0, 0);

    for (int kt = 0; kt < KT; ++kt) {
        cp_wait<0>();
        __syncthreads();
        if (kt + 1 < KT) LOAD(kt + 1, (kt + 1) & 1);

        const uint32_t base = sb + (kt & 1) * STG_D;
        #pragma unroll
        for (int ss = 0; ss < 2; ++ss) {
            const uint32_t kofs = ss * 32;
            uint32_t afh[4][4], afl[4][4];
            uint32_t b1[2][2], b3[2][2];
            #pragma unroll
            for (int mt = 0; mt < 4; ++mt) {
                uint32_t ad = base + (uint32_t)(wm*64 + mt*16 + lrow) * RSB
                            + kofs + lkb * 16;
                ldm4(afh[mt], ad);
                ldm4(afl[mt], ad + TILE1);
            }
            {
                uint32_t bd = base + 2*TILE1
                            + (uint32_t)(wn*16 + lrow) * RSB + kofs + lkb * 16;
                uint32_t r[4];
                ldm4(r, bd);
                b1[0][0]=r[0]; b1[0][1]=r[2]; b1[1][0]=r[1]; b1[1][1]=r[3];
                ldm4(r, bd + TILB1);
                b3[0][0]=r[0]; b3[0][1]=r[2]; b3[1][0]=r[1]; b3[1][1]=r[3];
            }
            #pragma unroll
            for (int mt = 0; mt < 4; ++mt)
                #pragma unroll
                for (int nt = 0; nt < 2; ++nt) {
                    mma16816(accG[mt][nt], afh[mt], b1[nt]);
                    mma16816(accG[mt][nt], afl[mt], b1[nt]);
                    mma16816(accV[mt][nt], afh[mt], b3[nt]);
                    mma16816(accV[mt][nt], afl[mt], b3[nt]);
                }
        }
        __syncthreads();
    }

    // epilogue: o = silu(gate) * val, split to fp16 (h, l), strided Kp
    const int g = lane >> 2, t = lane & 3;
    #pragma unroll
    for (int mt = 0; mt < 4; ++mt) {
        #pragma unroll
        for (int nt = 0; nt < 2; ++nt) {
            const int col  = nBase + wn*16 + nt*8 + t*2;
            const int row0 = mBase + wm*64 + mt*16 + g;
            #pragma unroll
            for (int half = 0; half < 2; ++half) {
                const int row = row0 + half * 8;
                float gg0 = accG[mt][nt][half*2],   gg1 = accG[mt][nt][half*2+1];
                float vv0 = accV[mt][nt][half*2],   vv1 = accV[mt][nt][half*2+1];
                float o0 = gg0 / (1.0f + __expf(-gg0)) * vv0;
                float o1 = gg1 / (1.0f + __expf(-gg1)) * vv1;
                f16 h0,l0,h1,l1;
                split1(o0,h0,l0); split1(o1,h1,l1);
                const size_t off = (size_t)row * Kp + col;
                *reinterpret_cast<__half2*>(Gh + off) = __half2(h0,h1);
                *reinterpret_cast<__half2*>(Gl + off) = __half2(l0,l1);
            }
        }
    }
}

// ------------------------------- launch -------------------------------------
extern "C" void kernel_launch(void* const* d_in, const int* in_sizes, int n_in,
                              void* d_out, int out_size)
{
    (void)in_sizes; (void)n_in; (void)out_size;
    const float* x        = (const float*)d_in[0];
    const float* log_lam  = (const float*)d_in[1];
    const float* B_w      = (const float*)d_in[2];
    const float* C_w      = (const float*)d_in[3];
    const float* D_skip   = (const float*)d_in[4];
    const float* ssm_w    = (const float*)d_in[5];
    const float* ffn_w    = (const float*)d_in[6];
    const float* w1       = (const float*)d_in[7];
    const float* w2       = (const float*)d_in[8];
    const float* w3       = (const float*)d_in[9];
    float* out = (float*)d_out;

    cudaFuncSetAttribute(gemm2_kernel<EPI_NONE>,
        cudaFuncAttributeMaxDynamicSharedMemorySize, SMEM_GEMM);
    cudaFuncSetAttribute(gemm2_kernel<EPI_SSM>,
        cudaFuncAttributeMaxDynamicSharedMemorySize, SMEM_GEMM);
    cudaFuncSetAttribute(gemm2_kernel<EPI_ADD>,
        cudaFuncAttributeMaxDynamicSharedMemorySize, SMEM_GEMM);
    cudaFuncSetAttribute(swiglu_kernel,
        cudaFuncAttributeMaxDynamicSharedMemorySize, SMEM_DUAL);

    float *u, *Bu, *hs, *x1, *Hc, *Hs;
    f16 *uh, *ul, *hsh, *hsl, *zh, *zl, *gh, *gl;
    f16 *Bw16, *Cw16, *w116, *w316, *w216;
    cudaGetSymbolAddress((void**)&u,    g_u);
    cudaGetSymbolAddress((void**)&Bu,   g_Bu);
    cudaGetSymbolAddress((void**)&hs,   g_hs);
    cudaGetSymbolAddress((void**)&x1,   g_x1);
    cudaGetSymbolAddress((void**)&Hc,   g_Hc);
    cudaGetSymbolAddress((void**)&Hs,   g_Hs);
    cudaGetSymbolAddress((void**)&uh,   g_uh);
    cudaGetSymbolAddress((void**)&ul,   g_ul);
    cudaGetSymbolAddress((void**)&hsh,  g_hsh);
    cudaGetSymbolAddress((void**)&hsl,  g_hsl);
    cudaGetSymbolAddress((void**)&zh,   g_zh);
    cudaGetSymbolAddress((void**)&zl,   g_zl);
    cudaGetSymbolAddress((void**)&gh,   g_gh);
    cudaGetSymbolAddress((void**)&gl,   g_gl);
    cudaGetSymbolAddress((void**)&Bw16, g_Bw16);
    cudaGetSymbolAddress((void**)&Cw16, g_Cw16);
    cudaGetSymbolAddress((void**)&w116, g_w116);
    cudaGetSymbolAddress((void**)&w316, g_w316);
    cudaGetSymbolAddress((void**)&w216, g_w216);

    // weight conversions (fp16, padded tails zero)
    {
        int n4 = NS * DM / 4;
        conv_kernel<<<(n4 + 255)/256, 256>>>((const float4*)B_w, (__half2*)Bw16, n4);
        n4 = DM * NS / 4;
        conv_kernel<<<(n4 + 255)/256, 256>>>((const float4*)C_w, (__half2*)Cw16, n4);
        int np = DFFP * DM;
        conv_padrow_kernel<<<(np + 255)/256, 256>>>(w1, w116, DFF, DFFP, DM);
        conv_padrow_kernel<<<(np + 255)/256, 256>>>(w3, w316, DFF, DFFP, DM);
        np = DM * DFFP;
        conv_padcol_kernel<<<(np + 255)/256, 256>>>(w2, w216, DM, DFF, DFFP);
    }

    // 1) u = rmsnorm(x, ssm_norm_w)  (fp32 + fp16 split)
    rmsnorm_split_kernel<<<MROWS, 256>>>(x, ssm_w, uh, ul, u);

    // 2) Bu = u @ B_w^T  [16384, 256], K=1024
    gemm2_kernel<EPI_NONE><<<dim3(NS/128, MROWS/128), 256, SMEM_GEMM>>>(
        uh, ul, Bw16, Bu, MROWS, NS, DM, nullptr, nullptr, nullptr);

    // 3) chunked diagonal scan -> hs (fp32), fixup+split fused
    scan_local_kernel<<<B_SZ * NCHUNK, NS>>>(Bu, hs, Hc, log_lam);
    scan_carry_kernel<<<B_SZ, NS>>>(Hc, Hs, log_lam);
    scan_fix_split_kernel<<<B_SZ * NCHUNK, NS>>>(hs, Hs, log_lam, hsh, hsl);

    // 4) x1 = x + hs @ C_w^T + D_skip * u  [16384, 1024], K=256
    gemm2_kernel<EPI_SSM><<<dim3(DM/128, MROWS/128), 256, SMEM_GEMM>>>(
        hsh, hsl, Cw16, x1, MROWS, DM, NS, x, u, D_skip);

    // 5) z = rmsnorm(x1, ffn_norm_w) (fp16 split only)
    rmsnorm_split_kernel<<<MROWS, 256>>>(x1, ffn_w, zh, zl, nullptr);

    // 6) g = split(silu(z@w1^T) * (z@w3^T))  [16384, 2752-padded], K=1024
    swiglu_kernel<<<dim3(DFFP/64, MROWS/128), 256, SMEM_DUAL>>>(
        zh, zl, w116, w316, gh, gl, MROWS, DFFP, DM);

    // 7) out = x1 + g @ w2^T  [16384, 1024], K=2752
    gemm2_kernel<EPI_ADD><<<dim3(DM/128, MROWS/128), 256, SMEM_GEMM>>>(
        gh, gl, w216, out, MROWS, DM, DFFP, x1, nullptr, nullptr);
}